// round 1
// baseline (speedup 1.0000x reference)
#include <cuda_runtime.h>
#include <cuda_bf16.h>
#include <math.h>

// Problem constants
#define NROW 8192
#define NFEAT 512
#define NHID 256
#define NCLASS 128

// Scratch (allocation-free rule: static __device__ globals)
__device__ float g_adj[(size_t)NROW * NROW];   // 256 MB
__device__ float g_A1[(size_t)NROW * NFEAT];   // adj @ fs
__device__ float g_A2[(size_t)NROW * NHID];    // adj @ x1

// ---------------------------------------------------------------------------
// Classic register-blocked SGEMM: C[M,N] = A[M,K] * B
//   BT = false: B is [K,N] row-major (NN)
//   BT = true : B is [N,K] row-major (NT, i.e. C = A * B^T)
// Requires: M % 128 == 0, N % 128 == 0, K % 16 == 0. 256 threads/block.
// ---------------------------------------------------------------------------
#define BM 128
#define BN 128
#define BK 16
#define TM 8
#define TN 8
#define PAD 4

template <bool BT>
__global__ __launch_bounds__(256, 2)
void sgemm_kernel(const float* __restrict__ A, const float* __restrict__ B,
                  float* __restrict__ C, int M, int N, int K) {
    __shared__ float As[BK][BM + PAD];
    __shared__ float Bs[BK][BN + PAD];

    const int tid = threadIdx.x;
    const int bm = blockIdx.y * BM;
    const int bn = blockIdx.x * BN;
    const int ty = tid / 16;   // 0..15  -> M micro-tile
    const int tx = tid % 16;   // 0..15  -> N micro-tile

    float acc[TM][TN];
#pragma unroll
    for (int i = 0; i < TM; i++)
#pragma unroll
        for (int j = 0; j < TN; j++) acc[i][j] = 0.0f;

    for (int kb = 0; kb < K; kb += BK) {
        // ---- load A tile: 128 rows x 16 cols, transposed into As[k][m]
#pragma unroll
        for (int it = 0; it < 2; it++) {
            int idx = tid + it * 256;          // 0..511 float4 slots
            int row = idx >> 2;                // 0..127
            int c4  = idx & 3;                 // 0..3
            float4 v = *(const float4*)(A + (size_t)(bm + row) * K + kb + c4 * 4);
            As[c4 * 4 + 0][row] = v.x;
            As[c4 * 4 + 1][row] = v.y;
            As[c4 * 4 + 2][row] = v.z;
            As[c4 * 4 + 3][row] = v.w;
        }
        // ---- load B tile
        if (BT) {
            // B is [N,K] row-major: tile rows are n, cols are k (contiguous)
#pragma unroll
            for (int it = 0; it < 2; it++) {
                int idx = tid + it * 256;
                int row = idx >> 2;            // n: 0..127
                int c4  = idx & 3;
                float4 v = *(const float4*)(B + (size_t)(bn + row) * K + kb + c4 * 4);
                Bs[c4 * 4 + 0][row] = v.x;
                Bs[c4 * 4 + 1][row] = v.y;
                Bs[c4 * 4 + 2][row] = v.z;
                Bs[c4 * 4 + 3][row] = v.w;
            }
        } else {
            // B is [K,N] row-major: tile rows are k, cols are n (contiguous)
#pragma unroll
            for (int it = 0; it < 2; it++) {
                int idx = tid + it * 256;
                int kr = idx >> 5;             // 0..15
                int c4 = idx & 31;             // 0..31
                float4 v = *(const float4*)(B + (size_t)(kb + kr) * N + bn + c4 * 4);
                Bs[kr][c4 * 4 + 0] = v.x;
                Bs[kr][c4 * 4 + 1] = v.y;
                Bs[kr][c4 * 4 + 2] = v.z;
                Bs[kr][c4 * 4 + 3] = v.w;
            }
        }
        __syncthreads();

#pragma unroll
        for (int k = 0; k < BK; k++) {
            float a[TM], b[TN];
#pragma unroll
            for (int i = 0; i < TM; i++) a[i] = As[k][ty * TM + i];
#pragma unroll
            for (int j = 0; j < TN; j++) b[j] = Bs[k][tx * TN + j];
#pragma unroll
            for (int i = 0; i < TM; i++)
#pragma unroll
                for (int j = 0; j < TN; j++) acc[i][j] = fmaf(a[i], b[j], acc[i][j]);
        }
        __syncthreads();
    }

    // ---- epilogue: vectorized store
#pragma unroll
    for (int i = 0; i < TM; i++) {
        int row = bm + ty * TM + i;
#pragma unroll
        for (int j = 0; j < TN; j += 4) {
            float4 v = make_float4(acc[i][j], acc[i][j + 1], acc[i][j + 2], acc[i][j + 3]);
            *(float4*)(C + (size_t)row * N + bn + tx * TN + j) = v;
        }
    }
}

// ---------------------------------------------------------------------------
// Row softmax over adj: one block per row, row cached in shared memory.
// N = 8192 floats per row = 32 KB smem.
// ---------------------------------------------------------------------------
__global__ void softmax_rows_kernel(float* __restrict__ adj, int N) {
    extern __shared__ float srow[];           // N floats
    __shared__ float warp_red[8];
    __shared__ float bcast;

    const int tid = threadIdx.x;
    const int lane = tid & 31;
    const int wid = tid >> 5;
    float* r = adj + (size_t)blockIdx.x * N;
    const int NV = N / 4;                      // float4 count

    // pass 1: load + local max
    float mx = -INFINITY;
    for (int i = tid; i < NV; i += blockDim.x) {
        float4 v = ((const float4*)r)[i];
        ((float4*)srow)[i] = v;
        mx = fmaxf(mx, fmaxf(fmaxf(v.x, v.y), fmaxf(v.z, v.w)));
    }
#pragma unroll
    for (int o = 16; o > 0; o >>= 1) mx = fmaxf(mx, __shfl_xor_sync(0xffffffffu, mx, o));
    if (lane == 0) warp_red[wid] = mx;
    __syncthreads();
    if (tid == 0) {
        float m = warp_red[0];
#pragma unroll
        for (int w = 1; w < 8; w++) m = fmaxf(m, warp_red[w]);
        bcast = m;
    }
    __syncthreads();
    mx = bcast;
    __syncthreads();

    // pass 2: exp + local sum
    float sum = 0.0f;
    for (int i = tid; i < NV; i += blockDim.x) {
        float4 v = ((const float4*)srow)[i];
        v.x = expf(v.x - mx); v.y = expf(v.y - mx);
        v.z = expf(v.z - mx); v.w = expf(v.w - mx);
        ((float4*)srow)[i] = v;
        sum += v.x + v.y + v.z + v.w;
    }
#pragma unroll
    for (int o = 16; o > 0; o >>= 1) sum += __shfl_xor_sync(0xffffffffu, sum, o);
    if (lane == 0) warp_red[wid] = sum;
    __syncthreads();
    if (tid == 0) {
        float s = 0.0f;
#pragma unroll
        for (int w = 0; w < 8; w++) s += warp_red[w];
        bcast = 1.0f / s;
    }
    __syncthreads();
    float inv = bcast;

    // pass 3: normalize + write back
    for (int i = tid; i < NV; i += blockDim.x) {
        float4 v = ((float4*)srow)[i];
        v.x *= inv; v.y *= inv; v.z *= inv; v.w *= inv;
        ((float4*)r)[i] = v;
    }
}

// ---------------------------------------------------------------------------
extern "C" void kernel_launch(void* const* d_in, const int* in_sizes, int n_in,
                              void* d_out, int out_size) {
    const float* fs = (const float*)d_in[0];   // [8192, 512]
    const float* ft = (const float*)d_in[1];   // [8192, 512]
    const float* w1 = (const float*)d_in[2];   // [256, 512]
    const float* w2 = (const float*)d_in[3];   // [128, 256]

    float* x1 = (float*)d_out;                         // [8192, 256]
    float* x2 = (float*)d_out + (size_t)NROW * NHID;   // [8192, 128]

    float *adj, *A1, *A2;
    cudaGetSymbolAddress((void**)&adj, g_adj);
    cudaGetSymbolAddress((void**)&A1, g_A1);
    cudaGetSymbolAddress((void**)&A2, g_A2);

    // 1) S = fs @ ft^T   [8192 x 8192], K=512   (NT)
    {
        dim3 grid(NROW / BN, NROW / BM);
        sgemm_kernel<true><<<grid, 256>>>(fs, ft, adj, NROW, NROW, NFEAT);
    }
    // 2) rowwise softmax in place
    softmax_rows_kernel<<<NROW, 256, NROW * sizeof(float)>>>(adj, NROW);

    // 3) A1 = adj @ fs   [8192 x 512], K=8192   (NN)
    {
        dim3 grid(NFEAT / BN, NROW / BM);
        sgemm_kernel<false><<<grid, 256>>>(adj, fs, A1, NROW, NFEAT, NROW);
    }
    // 4) x1 = A1 @ w1^T  [8192 x 256], K=512    (NT)
    {
        dim3 grid(NHID / BN, NROW / BM);
        sgemm_kernel<true><<<grid, 256>>>(A1, w1, x1, NROW, NHID, NFEAT);
    }
    // 5) A2 = adj @ x1   [8192 x 256], K=8192   (NN)
    {
        dim3 grid(NHID / BN, NROW / BM);
        sgemm_kernel<false><<<grid, 256>>>(adj, x1, A2, NROW, NHID, NROW);
    }
    // 6) x2 = A2 @ w2^T  [8192 x 128], K=256    (NT)
    {
        dim3 grid(NCLASS / BN, NROW / BM);
        sgemm_kernel<true><<<grid, 256>>>(A2, w2, x2, NROW, NCLASS, NHID);
    }
}

// round 3
// speedup vs baseline: 1.7952x; 1.7952x over previous
#include <cuda_runtime.h>
#include <cuda_bf16.h>
#include <cstdint>
#include <math.h>

#define NROW 8192
#define NFEAT 512
#define NHID 256
#define NCLASS 128

// Scratch (allocation-free rule: static __device__ globals)
__device__ float g_adj[(size_t)NROW * NROW];   // 256 MB
__device__ float g_A1[(size_t)NROW * NFEAT];
__device__ float g_A2[(size_t)NROW * NHID];

// ---------------------------------------------------------------------------
// mma.sync tf32 helpers (sm_80+ features: safe for the non-'a' PTX target)
// ---------------------------------------------------------------------------
__device__ __forceinline__ uint32_t f2tf32(float x) {
    uint32_t u;
    asm("cvt.rna.tf32.f32 %0, %1;" : "=r"(u) : "f"(x));
    return u;
}

__device__ __forceinline__ void mma_tf32(float& c0, float& c1, float& c2, float& c3,
                                         uint32_t a0, uint32_t a1, uint32_t a2, uint32_t a3,
                                         uint32_t b0, uint32_t b1) {
    asm volatile(
        "mma.sync.aligned.m16n8k8.row.col.f32.tf32.tf32.f32 "
        "{%0,%1,%2,%3}, {%4,%5,%6,%7}, {%8,%9}, {%0,%1,%2,%3};"
        : "+f"(c0), "+f"(c1), "+f"(c2), "+f"(c3)
        : "r"(a0), "r"(a1), "r"(a2), "r"(a3), "r"(b0), "r"(b1));
}

#define CP_ASYNC16(dst, src) \
    asm volatile("cp.async.cg.shared.global [%0], [%1], 16;" :: "r"(dst), "l"(src))
#define CP_COMMIT() asm volatile("cp.async.commit_group;" ::: "memory")
#define CP_WAIT1() asm volatile("cp.async.wait_group 1;" ::: "memory")

__device__ __forceinline__ uint32_t smem_u32(const void* p) {
    uint32_t a;
    asm("{ .reg .u64 t; cvta.to.shared.u64 t, %1; cvt.u32.u64 %0, t; }" : "=r"(a) : "l"(p));
    return a;
}

// ---------------------------------------------------------------------------
// tf32 mma.sync GEMM: C[M,N] = A[M,K] @ op(B)
//   BT=true : B is [N,K] row-major (C = A B^T)
//   BT=false: B is [K,N] row-major
//   SPLIT   : 3xTF32 hi/lo in registers (near-fp32)
// Tiles 128x128x32, 256 threads (8 warps, 2x4), warp tile 64x32.
// cp.async double-buffered. Requires M%128==0, N%128==0, K%32==0.
// ---------------------------------------------------------------------------
#define ASTRIDE 36           // floats per A-tile row (128 rows x 32 k + pad)
#define BTSTRIDE 36          // BT: [n][k]
#define BNSTRIDE 132         // NN: [k][n]
#define ATILE (128 * ASTRIDE)
#define BTTILE (128 * BTSTRIDE)
#define BNTILE (32 * BNSTRIDE)

template <bool BT, bool SPLIT>
__global__ void __launch_bounds__(256, 2)
mma_gemm_kernel(const float* __restrict__ A, const float* __restrict__ B,
                float* __restrict__ C, int M, int N, int K) {
    extern __shared__ float smem[];
    float* As = smem;                               // 2 x ATILE
    float* Bs = smem + 2 * ATILE;                   // 2 x (BT ? BTTILE : BNTILE)
    const int BTILE = BT ? BTTILE : BNTILE;

    const int tid = threadIdx.x;
    const int wid = tid >> 5;
    const int lane = tid & 31;
    const int warp_m = wid >> 2;                    // 0..1
    const int warp_n = wid & 3;                     // 0..3
    const int tr = lane >> 2;                       // 0..7
    const int tc = lane & 3;                        // 0..3
    const int bm = blockIdx.y * 128;
    const int bn = blockIdx.x * 128;

    // cp.async coordinates
    const int arow = tid >> 1, ahalf = tid & 1;     // A/B-T: 2 thr per 32-float row
    const int bkr = tid >> 3, bseg = tid & 7;       // B-NN: 8 thr per 128-float row

    const uint32_t sAs = smem_u32(As);
    const uint32_t sBs = smem_u32(Bs);

    float acc[4][4][4];
#pragma unroll
    for (int i = 0; i < 4; i++)
#pragma unroll
        for (int j = 0; j < 4; j++)
#pragma unroll
            for (int q = 0; q < 4; q++) acc[i][j][q] = 0.0f;

    const int niter = K / 32;

    // ---- tile loader
    auto load_tiles = [&](int buf, int kb) {
        // A tile: 128 rows x 32 floats
        {
            const float* src = A + (size_t)(bm + arow) * K + kb + ahalf * 16;
            uint32_t dst = sAs + (buf * ATILE + arow * ASTRIDE + ahalf * 16) * 4;
#pragma unroll
            for (int j = 0; j < 4; j++) CP_ASYNC16(dst + j * 16, src + j * 4);
        }
        if (BT) {
            const float* src = B + (size_t)(bn + arow) * K + kb + ahalf * 16;
            uint32_t dst = sBs + (buf * BTILE + arow * BTSTRIDE + ahalf * 16) * 4;
#pragma unroll
            for (int j = 0; j < 4; j++) CP_ASYNC16(dst + j * 16, src + j * 4);
        } else {
            const float* src = B + (size_t)(kb + bkr) * N + bn + bseg * 16;
            uint32_t dst = sBs + (buf * BTILE + bkr * BNSTRIDE + bseg * 16) * 4;
#pragma unroll
            for (int j = 0; j < 4; j++) CP_ASYNC16(dst + j * 16, src + j * 4);
        }
    };

    load_tiles(0, 0);
    CP_COMMIT();

    int buf = 0;
    for (int it = 0; it < niter; it++) {
        if (it + 1 < niter) load_tiles(buf ^ 1, (it + 1) * 32);
        CP_COMMIT();
        CP_WAIT1();
        __syncthreads();

        const float* At = As + buf * ATILE;
        const float* Bt = Bs + buf * BTILE;
        // per-thread fragment bases
        const float* ap0 = At + (warp_m * 64 + tr) * ASTRIDE + tc;
        const float* bp0 = BT ? (Bt + (warp_n * 32 + tr) * BTSTRIDE + tc)
                              : (Bt + tc * BNSTRIDE + warp_n * 32 + tr);

#pragma unroll
        for (int ks = 0; ks < 4; ks++) {
            // ---- A fragments (4 m-frags), hi/lo in registers
            uint32_t ah[4][4], al[4][4];
#pragma unroll
            for (int mf = 0; mf < 4; mf++) {
                const float* ap = ap0 + mf * 16 * ASTRIDE + ks * 8;
                float x0 = ap[0];
                float x1 = ap[8 * ASTRIDE];
                float x2 = ap[4];
                float x3 = ap[8 * ASTRIDE + 4];
                ah[mf][0] = f2tf32(x0); ah[mf][1] = f2tf32(x1);
                ah[mf][2] = f2tf32(x2); ah[mf][3] = f2tf32(x3);
                if (SPLIT) {
                    al[mf][0] = f2tf32(x0 - __uint_as_float(ah[mf][0]));
                    al[mf][1] = f2tf32(x1 - __uint_as_float(ah[mf][1]));
                    al[mf][2] = f2tf32(x2 - __uint_as_float(ah[mf][2]));
                    al[mf][3] = f2tf32(x3 - __uint_as_float(ah[mf][3]));
                }
            }
            // ---- B fragments (4 n-frags)
#pragma unroll
            for (int nf = 0; nf < 4; nf++) {
                float y0, y1;
                if (BT) {
                    const float* bp = bp0 + nf * 8 * BTSTRIDE + ks * 8;
                    y0 = bp[0];
                    y1 = bp[4];
                } else {
                    const float* bp = bp0 + ks * 8 * BNSTRIDE + nf * 8;
                    y0 = bp[0];
                    y1 = bp[4 * BNSTRIDE];
                }
                uint32_t bh0 = f2tf32(y0), bh1 = f2tf32(y1);
                uint32_t bl0 = 0, bl1 = 0;
                if (SPLIT) {
                    bl0 = f2tf32(y0 - __uint_as_float(bh0));
                    bl1 = f2tf32(y1 - __uint_as_float(bh1));
                }
#pragma unroll
                for (int mf = 0; mf < 4; mf++) {
                    if (SPLIT) {
                        mma_tf32(acc[mf][nf][0], acc[mf][nf][1], acc[mf][nf][2], acc[mf][nf][3],
                                 ah[mf][0], ah[mf][1], ah[mf][2], ah[mf][3], bl0, bl1);
                        mma_tf32(acc[mf][nf][0], acc[mf][nf][1], acc[mf][nf][2], acc[mf][nf][3],
                                 al[mf][0], al[mf][1], al[mf][2], al[mf][3], bh0, bh1);
                    }
                    mma_tf32(acc[mf][nf][0], acc[mf][nf][1], acc[mf][nf][2], acc[mf][nf][3],
                             ah[mf][0], ah[mf][1], ah[mf][2], ah[mf][3], bh0, bh1);
                }
            }
        }
        __syncthreads();
        buf ^= 1;
    }

    // ---- epilogue: c0/c1 at (row, 2*tc), c2/c3 at (row+8, 2*tc)
#pragma unroll
    for (int mf = 0; mf < 4; mf++) {
#pragma unroll
        for (int nf = 0; nf < 4; nf++) {
            int r0 = bm + warp_m * 64 + mf * 16 + tr;
            int col = bn + warp_n * 32 + nf * 8 + 2 * tc;
            float2 v0 = make_float2(acc[mf][nf][0], acc[mf][nf][1]);
            float2 v1 = make_float2(acc[mf][nf][2], acc[mf][nf][3]);
            *(float2*)(C + (size_t)r0 * N + col) = v0;
            *(float2*)(C + (size_t)(r0 + 8) * N + col) = v1;
        }
    }
}

// ---------------------------------------------------------------------------
// Row softmax over adj, in place. One block per row (row cached in smem).
// ---------------------------------------------------------------------------
__global__ void softmax_rows_kernel(float* __restrict__ adj, int N) {
    extern __shared__ float srow[];
    __shared__ float warp_red[8];
    __shared__ float bcast;

    const int tid = threadIdx.x;
    const int lane = tid & 31;
    const int wid = tid >> 5;
    float* r = adj + (size_t)blockIdx.x * N;
    const int NV = N / 4;

    float mx = -INFINITY;
    for (int i = tid; i < NV; i += blockDim.x) {
        float4 v = ((const float4*)r)[i];
        ((float4*)srow)[i] = v;
        mx = fmaxf(mx, fmaxf(fmaxf(v.x, v.y), fmaxf(v.z, v.w)));
    }
#pragma unroll
    for (int o = 16; o > 0; o >>= 1) mx = fmaxf(mx, __shfl_xor_sync(0xffffffffu, mx, o));
    if (lane == 0) warp_red[wid] = mx;
    __syncthreads();
    if (tid == 0) {
        float m = warp_red[0];
#pragma unroll
        for (int w = 1; w < 8; w++) m = fmaxf(m, warp_red[w]);
        bcast = m;
    }
    __syncthreads();
    mx = bcast;
    __syncthreads();

    float sum = 0.0f;
    for (int i = tid; i < NV; i += blockDim.x) {
        float4 v = ((const float4*)srow)[i];
        v.x = expf(v.x - mx); v.y = expf(v.y - mx);
        v.z = expf(v.z - mx); v.w = expf(v.w - mx);
        ((float4*)srow)[i] = v;
        sum += v.x + v.y + v.z + v.w;
    }
#pragma unroll
    for (int o = 16; o > 0; o >>= 1) sum += __shfl_xor_sync(0xffffffffu, sum, o);
    if (lane == 0) warp_red[wid] = sum;
    __syncthreads();
    if (tid == 0) {
        float s = 0.0f;
#pragma unroll
        for (int w = 0; w < 8; w++) s += warp_red[w];
        bcast = 1.0f / s;
    }
    __syncthreads();
    float inv = bcast;

    for (int i = tid; i < NV; i += blockDim.x) {
        float4 v = ((float4*)srow)[i];
        v.x *= inv; v.y *= inv; v.z *= inv; v.w *= inv;
        ((float4*)r)[i] = v;
    }
}

// ---------------------------------------------------------------------------
extern "C" void kernel_launch(void* const* d_in, const int* in_sizes, int n_in,
                              void* d_out, int out_size) {
    const float* fs = (const float*)d_in[0];   // [8192, 512]
    const float* ft = (const float*)d_in[1];   // [8192, 512]
    const float* w1 = (const float*)d_in[2];   // [256, 512]
    const float* w2 = (const float*)d_in[3];   // [128, 256]

    float* x1 = (float*)d_out;                         // [8192, 256]
    float* x2 = (float*)d_out + (size_t)NROW * NHID;   // [8192, 128]

    float *adj, *A1, *A2;
    cudaGetSymbolAddress((void**)&adj, g_adj);
    cudaGetSymbolAddress((void**)&A1, g_A1);
    cudaGetSymbolAddress((void**)&A2, g_A2);

    const int SMEM_T = (2 * ATILE + 2 * BTTILE) * 4;   // 73728 B
    const int SMEM_N = (2 * ATILE + 2 * BNTILE) * 4;   // 70656 B
    cudaFuncSetAttribute(mma_gemm_kernel<true, true>,
                         cudaFuncAttributeMaxDynamicSharedMemorySize, SMEM_T);
    cudaFuncSetAttribute(mma_gemm_kernel<false, false>,
                         cudaFuncAttributeMaxDynamicSharedMemorySize, SMEM_N);

    // 1) S = fs @ ft^T (3xTF32 split: feeds exp)
    mma_gemm_kernel<true, true><<<dim3(NROW / 128, NROW / 128), 256, SMEM_T>>>(
        fs, ft, adj, NROW, NROW, NFEAT);

    // 2) rowwise softmax in place
    softmax_rows_kernel<<<NROW, 256, NROW * sizeof(float)>>>(adj, NROW);

    // 3) A1 = adj @ fs (NN, 1xTF32)
    mma_gemm_kernel<false, false><<<dim3(NFEAT / 128, NROW / 128), 256, SMEM_N>>>(
        adj, fs, A1, NROW, NFEAT, NROW);

    // 4) x1 = A1 @ w1^T (3xTF32)
    mma_gemm_kernel<true, true><<<dim3(NHID / 128, NROW / 128), 256, SMEM_T>>>(
        A1, w1, x1, NROW, NHID, NFEAT);

    // 5) A2 = adj @ x1 (NN, 1xTF32)
    mma_gemm_kernel<false, false><<<dim3(NHID / 128, NROW / 128), 256, SMEM_N>>>(
        adj, x1, A2, NROW, NHID, NROW);

    // 6) x2 = A2 @ w2^T (3xTF32)
    mma_gemm_kernel<true, true><<<dim3(NCLASS / 128, NROW / 128), 256, SMEM_T>>>(
        A2, w2, x2, NROW, NCLASS, NHID);
}

// round 4
// speedup vs baseline: 3.6274x; 2.0206x over previous
#include <cuda_runtime.h>
#include <cuda_fp16.h>
#include <cstdint>
#include <math.h>

#define NROW 8192
#define NFEAT 512
#define NHID 256
#define NCLASS 128

// ---------------------------------------------------------------------------
// Static device scratch (allocation-free rule)
// ---------------------------------------------------------------------------
__device__ __align__(16) float  g_adj[(size_t)NROW * NROW];     // fp32 logits, 256MB
__device__ __align__(16) __half g_adjh[(size_t)NROW * NROW];    // fp16 softmax weights, 128MB
__device__ __align__(16) __half g_fsh[(size_t)NROW * NFEAT];
__device__ __align__(16) __half g_fsl[(size_t)NROW * NFEAT];
__device__ __align__(16) __half g_fth[(size_t)NROW * NFEAT];
__device__ __align__(16) __half g_ftl[(size_t)NROW * NFEAT];
__device__ __align__(16) __half g_fsT[(size_t)NFEAT * NROW];    // fs^T fp16
__device__ __align__(16) float  g_A1[(size_t)NROW * NFEAT];
__device__ __align__(16) __half g_A1h[(size_t)NROW * NFEAT];
__device__ __align__(16) __half g_A1l[(size_t)NROW * NFEAT];
__device__ __align__(16) __half g_x1T[(size_t)NHID * NROW];     // x1^T fp16
__device__ __align__(16) float  g_A2[(size_t)NROW * NHID];
__device__ __align__(16) __half g_A2h[(size_t)NROW * NHID];
__device__ __align__(16) __half g_A2l[(size_t)NROW * NHID];
__device__ __align__(16) __half g_w1h[(size_t)NHID * NFEAT];
__device__ __align__(16) __half g_w1l[(size_t)NHID * NFEAT];
__device__ __align__(16) __half g_w2h[(size_t)NCLASS * NHID];
__device__ __align__(16) __half g_w2l[(size_t)NCLASS * NHID];

// ---------------------------------------------------------------------------
// PTX helpers (all sm_80-era features; safe for the non-'a' PTX target)
// ---------------------------------------------------------------------------
__device__ __forceinline__ uint32_t smem_u32(const void* p) {
    uint32_t a;
    asm("{ .reg .u64 t; cvta.to.shared.u64 t, %1; cvt.u32.u64 %0, t; }" : "=r"(a) : "l"(p));
    return a;
}

#define CP_ASYNC16(dst, src) \
    asm volatile("cp.async.cg.shared.global [%0], [%1], 16;" :: "r"(dst), "l"(src))
#define CP_COMMIT() asm volatile("cp.async.commit_group;" ::: "memory")
#define CP_WAIT1()  asm volatile("cp.async.wait_group 1;" ::: "memory")

__device__ __forceinline__ void ldsm4(uint32_t* r, uint32_t addr) {
    asm volatile("ldmatrix.sync.aligned.m8n8.x4.shared.b16 {%0,%1,%2,%3}, [%4];"
                 : "=r"(r[0]), "=r"(r[1]), "=r"(r[2]), "=r"(r[3]) : "r"(addr));
}
__device__ __forceinline__ void ldsm2(uint32_t& r0, uint32_t& r1, uint32_t addr) {
    asm volatile("ldmatrix.sync.aligned.m8n8.x2.shared.b16 {%0,%1}, [%2];"
                 : "=r"(r0), "=r"(r1) : "r"(addr));
}

__device__ __forceinline__ void mma_f16(float* c, const uint32_t* a, uint32_t b0, uint32_t b1) {
    asm volatile(
        "mma.sync.aligned.m16n8k16.row.col.f32.f16.f16.f32 "
        "{%0,%1,%2,%3}, {%4,%5,%6,%7}, {%8,%9}, {%0,%1,%2,%3};"
        : "+f"(c[0]), "+f"(c[1]), "+f"(c[2]), "+f"(c[3])
        : "r"(a[0]), "r"(a[1]), "r"(a[2]), "r"(a[3]), "r"(b0), "r"(b1));
}

// ---------------------------------------------------------------------------
// fp16 HMMA GEMM: C[M,N] = A[M,K] @ B[N,K]^T   (all operands k-contiguous fp16)
//   TERMS=3: C = Ah*Bh^T + Ah*Bl^T + Al*Bh^T (split, near-fp32)
//   TERMS=1: C = Ah*Bh^T
// Tile 128x128xKT, 256 threads (8 warps 2x4), warp tile 64x32.
// smem rows padded to CPR+1 16B granules -> ldmatrix conflict-free.
// Requires M%128==0, N%128==0, K%KT==0.
// ---------------------------------------------------------------------------
template <int TERMS, int KT>
__global__ void __launch_bounds__(256, 2)
hgemm_kernel(const __half* __restrict__ Ah, const __half* __restrict__ Al,
             const __half* __restrict__ Bh, const __half* __restrict__ Bl,
             float* __restrict__ C, int M, int N, int K) {
    constexpr int CPR = KT / 8;            // 16B chunks per row
    constexpr int PITCH = (CPR + 1) * 16;  // padded row bytes
    constexpr int TILE = 128 * PITCH;      // one operand tile
    constexpr int NTO = (TERMS == 3) ? 2 : 1;
    constexpr int STG = 2 * NTO * TILE;    // stage bytes (A tiles + B tiles)
    constexpr int HC = CPR / 2;            // chunks per thread per tile

    extern __shared__ char smem[];
    const uint32_t smb = smem_u32(smem);

    const int tid = threadIdx.x;
    const int wid = tid >> 5;
    const int lane = tid & 31;
    const int warp_m = wid >> 2;
    const int warp_n = wid & 3;
    const int bm = blockIdx.y * 128;
    const int bn = blockIdx.x * 128;

    // ldmatrix lane coordinates
    const int ra = (lane & 7) + ((lane >> 3) & 1) * 8;  // A matrix row within 16
    const int ca = lane >> 4;                           // A k-chunk select (0/1)
    const int rb = lane & 7;                            // B n-row within 8
    const int cb2 = (lane >> 3) & 1;                    // B k-chunk select

    // loader coordinates
    const int lr = tid >> 1;
    const int lc0 = (tid & 1) * HC;

    float acc[4][4][4];
#pragma unroll
    for (int i = 0; i < 4; i++)
#pragma unroll
        for (int j = 0; j < 4; j++)
#pragma unroll
            for (int q = 0; q < 4; q++) acc[i][j][q] = 0.0f;

    auto load_stage = [&](int buf, int kb) {
        uint32_t d = smb + buf * STG;
        const __half* pa = Ah + (size_t)(bm + lr) * K + kb;
        const __half* pb = Bh + (size_t)(bn + lr) * K + kb;
        uint32_t rowd = d + lr * PITCH;
        uint32_t bOff = NTO * TILE;
#pragma unroll
        for (int j = 0; j < HC; j++) {
            int ch = lc0 + j;
            CP_ASYNC16(rowd + ch * 16, pa + ch * 8);
            CP_ASYNC16(rowd + bOff + ch * 16, pb + ch * 8);
        }
        if (TERMS == 3) {
            const __half* qa = Al + (size_t)(bm + lr) * K + kb;
            const __half* qb = Bl + (size_t)(bn + lr) * K + kb;
#pragma unroll
            for (int j = 0; j < HC; j++) {
                int ch = lc0 + j;
                CP_ASYNC16(rowd + TILE + ch * 16, qa + ch * 8);
                CP_ASYNC16(rowd + bOff + TILE + ch * 16, qb + ch * 8);
            }
        }
    };

    const int niter = K / KT;
    load_stage(0, 0);
    CP_COMMIT();

    int buf = 0;
    for (int it = 0; it < niter; it++) {
        if (it + 1 < niter) load_stage(buf ^ 1, (it + 1) * KT);
        CP_COMMIT();
        CP_WAIT1();
        __syncthreads();

        const uint32_t aH = smb + buf * STG;
        const uint32_t aL = aH + TILE;
        const uint32_t bH = aH + NTO * TILE;
        const uint32_t bL = bH + TILE;

#pragma unroll
        for (int ks = 0; ks < KT / 16; ks++) {
            uint32_t ah[4][4], al_[4][4];
            const uint32_t aco = (uint32_t)(2 * ks + ca) * 16;
#pragma unroll
            for (int mf = 0; mf < 4; mf++) {
                uint32_t ro = (uint32_t)(warp_m * 64 + mf * 16 + ra) * PITCH;
                ldsm4(ah[mf], aH + ro + aco);
                if (TERMS == 3) ldsm4(al_[mf], aL + ro + aco);
            }
            const uint32_t bco = (uint32_t)(2 * ks + cb2) * 16;
#pragma unroll
            for (int nf = 0; nf < 4; nf++) {
                uint32_t ro = (uint32_t)(warp_n * 32 + nf * 8 + rb) * PITCH;
                uint32_t bh0, bh1, bl0, bl1;
                ldsm2(bh0, bh1, bH + ro + bco);
                if (TERMS == 3) ldsm2(bl0, bl1, bL + ro + bco);
#pragma unroll
                for (int mf = 0; mf < 4; mf++) {
                    mma_f16(acc[mf][nf], ah[mf], bh0, bh1);
                    if (TERMS == 3) {
                        mma_f16(acc[mf][nf], ah[mf], bl0, bl1);
                        mma_f16(acc[mf][nf], al_[mf], bh0, bh1);
                    }
                }
            }
        }
        __syncthreads();
        buf ^= 1;
    }

    // epilogue: c0/c1 at (row, 2*tc), c2/c3 at (row+8, 2*tc)
    const int tr = lane >> 2;
    const int tc = lane & 3;
#pragma unroll
    for (int mf = 0; mf < 4; mf++) {
#pragma unroll
        for (int nf = 0; nf < 4; nf++) {
            int r0 = bm + warp_m * 64 + mf * 16 + tr;
            int col = bn + warp_n * 32 + nf * 8 + 2 * tc;
            *(float2*)(C + (size_t)r0 * N + col) = make_float2(acc[mf][nf][0], acc[mf][nf][1]);
            *(float2*)(C + (size_t)(r0 + 8) * N + col) = make_float2(acc[mf][nf][2], acc[mf][nf][3]);
        }
    }
}

// ---------------------------------------------------------------------------
// fp32 -> (hi fp16, lo fp16) elementwise split, vectorized
// ---------------------------------------------------------------------------
__global__ void split_kernel(const float* __restrict__ src, __half* __restrict__ h,
                             __half* __restrict__ l, int n4) {
    int i = blockIdx.x * blockDim.x + threadIdx.x;
    if (i >= n4) return;
    float4 v = ((const float4*)src)[i];
    float hx = __half2float(__float2half_rn(v.x));
    float hy = __half2float(__float2half_rn(v.y));
    float hz = __half2float(__float2half_rn(v.z));
    float hw = __half2float(__float2half_rn(v.w));
    __half2* hp = (__half2*)h;
    __half2* lp = (__half2*)l;
    hp[i * 2] = __floats2half2_rn(hx, hy);
    hp[i * 2 + 1] = __floats2half2_rn(hz, hw);
    lp[i * 2] = __floats2half2_rn(v.x - hx, v.y - hy);
    lp[i * 2 + 1] = __floats2half2_rn(v.z - hz, v.w - hw);
}

// ---------------------------------------------------------------------------
// fp32 [R][C] -> fp16 transposed [C][R]
// ---------------------------------------------------------------------------
__global__ void transpose_h_kernel(const float* __restrict__ src, __half* __restrict__ dst,
                                   int R, int C) {
    __shared__ float tile[32][33];
    int c = blockIdx.x * 32 + threadIdx.x;
    int r = blockIdx.y * 32 + threadIdx.y;
#pragma unroll
    for (int j = 0; j < 32; j += 8)
        tile[threadIdx.y + j][threadIdx.x] = src[(size_t)(r + j) * C + c];
    __syncthreads();
    int rr = blockIdx.y * 32 + threadIdx.x;   // output col (= src row)
    int cc = blockIdx.x * 32 + threadIdx.y;   // output row (= src col)
#pragma unroll
    for (int j = 0; j < 32; j += 8)
        dst[(size_t)(cc + j) * R + rr] = __float2half_rn(tile[threadIdx.x][threadIdx.y + j]);
}

// ---------------------------------------------------------------------------
// Row softmax: read fp32 logits, write normalized weights as fp16.
// ---------------------------------------------------------------------------
__global__ void softmax_rows_kernel(const float* __restrict__ adj, __half* __restrict__ out,
                                    int N) {
    extern __shared__ float srow[];
    __shared__ float warp_red[8];
    __shared__ float bcast;

    const int tid = threadIdx.x;
    const int lane = tid & 31;
    const int wid = tid >> 5;
    const float* r = adj + (size_t)blockIdx.x * N;
    __half* o = out + (size_t)blockIdx.x * N;
    const int NV = N / 4;

    float mx = -INFINITY;
    for (int i = tid; i < NV; i += blockDim.x) {
        float4 v = ((const float4*)r)[i];
        ((float4*)srow)[i] = v;
        mx = fmaxf(mx, fmaxf(fmaxf(v.x, v.y), fmaxf(v.z, v.w)));
    }
#pragma unroll
    for (int off = 16; off > 0; off >>= 1) mx = fmaxf(mx, __shfl_xor_sync(0xffffffffu, mx, off));
    if (lane == 0) warp_red[wid] = mx;
    __syncthreads();
    if (tid == 0) {
        float m = warp_red[0];
#pragma unroll
        for (int w = 1; w < 8; w++) m = fmaxf(m, warp_red[w]);
        bcast = m;
    }
    __syncthreads();
    mx = bcast;
    __syncthreads();

    float sum = 0.0f;
    for (int i = tid; i < NV; i += blockDim.x) {
        float4 v = ((const float4*)srow)[i];
        v.x = __expf(v.x - mx); v.y = __expf(v.y - mx);
        v.z = __expf(v.z - mx); v.w = __expf(v.w - mx);
        ((float4*)srow)[i] = v;
        sum += v.x + v.y + v.z + v.w;
    }
#pragma unroll
    for (int off = 16; off > 0; off >>= 1) sum += __shfl_xor_sync(0xffffffffu, sum, off);
    if (lane == 0) warp_red[wid] = sum;
    __syncthreads();
    if (tid == 0) {
        float s = 0.0f;
#pragma unroll
        for (int w = 0; w < 8; w++) s += warp_red[w];
        bcast = 1.0f / s;
    }
    __syncthreads();
    float inv = bcast;

    for (int i = tid; i < NV; i += blockDim.x) {
        float4 v = ((float4*)srow)[i];
        ((__half2*)o)[i * 2] = __floats2half2_rn(v.x * inv, v.y * inv);
        ((__half2*)o)[i * 2 + 1] = __floats2half2_rn(v.z * inv, v.w * inv);
    }
}

// ---------------------------------------------------------------------------
extern "C" void kernel_launch(void* const* d_in, const int* in_sizes, int n_in,
                              void* d_out, int out_size) {
    const float* fs = (const float*)d_in[0];
    const float* ft = (const float*)d_in[1];
    const float* w1 = (const float*)d_in[2];
    const float* w2 = (const float*)d_in[3];

    float* x1 = (float*)d_out;
    float* x2 = (float*)d_out + (size_t)NROW * NHID;

    float *adj, *A1, *A2;
    __half *adjh, *fsh, *fsl, *fth, *ftl, *fsT, *A1h, *A1l, *x1T, *A2h, *A2l;
    __half *w1h, *w1l, *w2h, *w2l;
    cudaGetSymbolAddress((void**)&adj, g_adj);
    cudaGetSymbolAddress((void**)&adjh, g_adjh);
    cudaGetSymbolAddress((void**)&fsh, g_fsh);
    cudaGetSymbolAddress((void**)&fsl, g_fsl);
    cudaGetSymbolAddress((void**)&fth, g_fth);
    cudaGetSymbolAddress((void**)&ftl, g_ftl);
    cudaGetSymbolAddress((void**)&fsT, g_fsT);
    cudaGetSymbolAddress((void**)&A1, g_A1);
    cudaGetSymbolAddress((void**)&A1h, g_A1h);
    cudaGetSymbolAddress((void**)&A1l, g_A1l);
    cudaGetSymbolAddress((void**)&x1T, g_x1T);
    cudaGetSymbolAddress((void**)&A2, g_A2);
    cudaGetSymbolAddress((void**)&A2h, g_A2h);
    cudaGetSymbolAddress((void**)&A2l, g_A2l);
    cudaGetSymbolAddress((void**)&w1h, g_w1h);
    cudaGetSymbolAddress((void**)&w1l, g_w1l);
    cudaGetSymbolAddress((void**)&w2h, g_w2h);
    cudaGetSymbolAddress((void**)&w2l, g_w2l);

    constexpr int SMEM_SPLIT = 2 * 2 * 2 * (128 * ((32 / 8 + 1) * 16));  // 81920
    constexpr int SMEM_1X = 2 * 1 * 2 * (128 * ((64 / 8 + 1) * 16));     // 73728
    cudaFuncSetAttribute(hgemm_kernel<3, 32>,
                         cudaFuncAttributeMaxDynamicSharedMemorySize, SMEM_SPLIT);
    cudaFuncSetAttribute(hgemm_kernel<1, 64>,
                         cudaFuncAttributeMaxDynamicSharedMemorySize, SMEM_1X);

    // ---- pre-pass: splits + transpose
    {
        int n4 = NROW * NFEAT / 4;
        split_kernel<<<(n4 + 255) / 256, 256>>>(fs, fsh, fsl, n4);
        split_kernel<<<(n4 + 255) / 256, 256>>>(ft, fth, ftl, n4);
        int nw1 = NHID * NFEAT / 4;
        split_kernel<<<(nw1 + 255) / 256, 256>>>(w1, w1h, w1l, nw1);
        int nw2 = NCLASS * NHID / 4;
        split_kernel<<<(nw2 + 255) / 256, 256>>>(w2, w2h, w2l, nw2);
        transpose_h_kernel<<<dim3(NFEAT / 32, NROW / 32), dim3(32, 8)>>>(fs, fsT, NROW, NFEAT);
    }

    // 1) S = fs @ ft^T  (fp16 x3 split -> fp32 logits)
    hgemm_kernel<3, 32><<<dim3(NROW / 128, NROW / 128), 256, SMEM_SPLIT>>>(
        fsh, fsl, fth, ftl, adj, NROW, NROW, NFEAT);

    // 2) softmax -> fp16 weights
    softmax_rows_kernel<<<NROW, 256, NROW * sizeof(float)>>>(adj, adjh, NROW);

    // 3) A1 = adj @ fs  == adjh[M,K] @ fsT[N,K]^T  (fp16 1x)
    hgemm_kernel<1, 64><<<dim3(NFEAT / 128, NROW / 128), 256, SMEM_1X>>>(
        adjh, nullptr, fsT, nullptr, A1, NROW, NFEAT, NROW);

    // 4) x1 = A1 @ w1^T (fp16 x3)
    {
        int n4 = NROW * NFEAT / 4;
        split_kernel<<<(n4 + 255) / 256, 256>>>(A1, A1h, A1l, n4);
    }
    hgemm_kernel<3, 32><<<dim3(NHID / 128, NROW / 128), 256, SMEM_SPLIT>>>(
        A1h, A1l, w1h, w1l, x1, NROW, NHID, NFEAT);

    // 5) A2 = adj @ x1 == adjh @ x1T^T (fp16 1x)
    transpose_h_kernel<<<dim3(NHID / 32, NROW / 32), dim3(32, 8)>>>(x1, x1T, NROW, NHID);
    hgemm_kernel<1, 64><<<dim3(NHID / 128, NROW / 128), 256, SMEM_1X>>>(
        adjh, nullptr, x1T, nullptr, A2, NROW, NHID, NROW);

    // 6) x2 = A2 @ w2^T (fp16 x3)
    {
        int n4 = NROW * NHID / 4;
        split_kernel<<<(n4 + 255) / 256, 256>>>(A2, A2h, A2l, n4);
    }
    hgemm_kernel<3, 32><<<dim3(NCLASS / 128, NROW / 128), 256, SMEM_SPLIT>>>(
        A2h, A2l, w2h, w2l, x2, NROW, NCLASS, NHID);
}